// round 14
// baseline (speedup 1.0000x reference)
#include <cuda_runtime.h>
#include <cuda_fp16.h>

// Problem constants
constexpr int B_  = 2;
constexpr int T_  = 2048;
constexpr int C_  = 1024;
constexpr int H_  = 16;
constexpr int HS_ = 64;
constexpr int M_  = B_ * T_;      // 4096
constexpr int N1_ = 3 * C_;       // 3072

// combined softmax scale: c^-0.5 * log2(e), folded into Q at GEMM1 epilogue
constexpr float QSC_ = 0.03125f * 1.4426950408889634f;

// Scratch (device globals: allocation-free rule)
__device__ __half g_qkvh[M_ * N1_];   // fp16 qkv [4096,3072] (K|Q|V), Q pre-scaled
__device__ __half g_atth[M_ * C_];    // fp16 attention out [4096,1024]
__device__ __half g_Xh  [M_  * C_];   // X fp16 [4096,1024]
__device__ __half g_WqT [N1_ * C_];   // W_qkv^T fp16 [3072,1024]
__device__ __half g_WpT [C_  * C_];   // W_proj^T fp16 [1024,1024]

// ---------------------------------------------------------------------------
// PTX helpers (baseline ISA only: must compile for virtual compute_103)
// ---------------------------------------------------------------------------
__device__ __forceinline__ unsigned smem_u32(const void* p) {
    unsigned a;
    asm("{ .reg .u64 t; cvta.to.shared.u64 t, %1; cvt.u32.u64 %0, t; }" : "=r"(a) : "l"(p));
    return a;
}
__device__ __forceinline__ void ldm4(unsigned* r, unsigned addr) {
    asm volatile("ldmatrix.sync.aligned.m8n8.x4.shared.b16 {%0,%1,%2,%3}, [%4];"
                 : "=r"(r[0]), "=r"(r[1]), "=r"(r[2]), "=r"(r[3]) : "r"(addr));
}
__device__ __forceinline__ void ldm4t(unsigned* r, unsigned addr) {
    asm volatile("ldmatrix.sync.aligned.m8n8.x4.trans.shared.b16 {%0,%1,%2,%3}, [%4];"
                 : "=r"(r[0]), "=r"(r[1]), "=r"(r[2]), "=r"(r[3]) : "r"(addr));
}
__device__ __forceinline__ void mma_f16(float* c, const unsigned* a,
                                        unsigned b0, unsigned b1) {
    asm volatile("mma.sync.aligned.m16n8k16.row.col.f32.f16.f16.f32 "
                 "{%0,%1,%2,%3}, {%4,%5,%6,%7}, {%8,%9}, {%0,%1,%2,%3};"
                 : "+f"(c[0]), "+f"(c[1]), "+f"(c[2]), "+f"(c[3])
                 : "r"(a[0]), "r"(a[1]), "r"(a[2]), "r"(a[3]), "r"(b0), "r"(b1));
}
__device__ __forceinline__ void cpasync16(unsigned dst, const void* src) {
    asm volatile("cp.async.cg.shared.global [%0], [%1], 16;" :: "r"(dst), "l"(src));
}
__device__ __forceinline__ float ex2(float x) {
    float y; asm("ex2.approx.f32 %0, %1;" : "=f"(y) : "f"(x)); return y;
}
__device__ __forceinline__ unsigned h2pack(float lo, float hi) {
    __half2 h = __floats2half2_rn(lo, hi);
    return *(unsigned*)&h;
}

// ---------------------------------------------------------------------------
// Conversion kernels: fp32 -> fp16
// ---------------------------------------------------------------------------
__global__ __launch_bounds__(256)
void conv_f2h_kernel(const float* __restrict__ in, __half* __restrict__ out)
{
    int i = blockIdx.x * blockDim.x + threadIdx.x;   // over n/4 float4s
    float4 v = ((const float4*)in)[i];
    ((__half2*)out)[2 * i]     = __floats2half2_rn(v.x, v.y);
    ((__half2*)out)[2 * i + 1] = __floats2half2_rn(v.z, v.w);
}

// W [K,N] row-major (K=C_) -> out [N, C_] fp16 transposed
__global__ __launch_bounds__(256)
void conv_wT_h_kernel(const float* __restrict__ in, __half* __restrict__ out, int N)
{
    __shared__ float ts[32][33];
    int n0 = blockIdx.x * 32, k0 = blockIdx.y * 32;
    int tx = threadIdx.x, ty = threadIdx.y;  // 32x8
    #pragma unroll
    for (int i = 0; i < 32; i += 8)
        ts[ty + i][tx] = in[(size_t)(k0 + ty + i) * N + n0 + tx];
    __syncthreads();
    #pragma unroll
    for (int i = 0; i < 32; i += 8) {
        int n = n0 + ty + i, k = k0 + tx;
        out[(size_t)n * C_ + k] = __float2half_rn(ts[tx][ty + i]);
    }
}

// ---------------------------------------------------------------------------
// Tensor-core GEMM via mma.sync (fp16 in, fp32 accum), K = C_ = 1024:
//   C[M,N] = A[M,C_] @ B[N,C_]^T.  128x128 CTA tile, BK=32, 8 warps.
// 3-stage cp.async pipeline (global->smem direct, no register staging).
// Output: fp32 (Cm) or fp16 (Ch, with Q-segment pre-scale for attention).
// ---------------------------------------------------------------------------
constexpr int LDA_ = 40;                         // fp16 stride: conflict-free ldmatrix
constexpr int GSTAGES = 3;
constexpr int GTILE_H = 128 * LDA_;              // halves per operand per stage
constexpr int GSTAGE_BYTES = 2 * GTILE_H * 2;    // A+B per stage, bytes (20480)
constexpr int GEMM_SMEM_BYTES = GSTAGES * GSTAGE_BYTES;  // 61440

__global__ __launch_bounds__(256)
void gemm_mma_h_kernel(const __half* __restrict__ A,
                       const __half* __restrict__ Bm,
                       float* __restrict__ Cm, __half* __restrict__ Ch, int N)
{
    extern __shared__ __align__(16) __half sm[];
    const unsigned sbase = smem_u32(sm);

    const int tid = threadIdx.x, lane = tid & 31, wid = tid >> 5;
    const int wm = (wid & 1) * 64, wn = (wid >> 1) * 32;
    const int bm = blockIdx.y * 128, bn = blockIdx.x * 128;

    const __half* Ag = A  + (size_t)bm * C_;
    const __half* Bg = Bm + (size_t)bn * C_;

    const int lr = tid >> 2, lseg = tid & 3;

    auto issue = [&](int kt, int s) {
        const int kpos = kt * 32;
        const unsigned abase = sbase + s * GSTAGE_BYTES;
        #pragma unroll
        for (int u = 0; u < 2; u++) {
            int row = lr + u * 64;
            unsigned off = (unsigned)(row * LDA_ + lseg * 8) * 2;
            cpasync16(abase + off,               Ag + (size_t)row * C_ + kpos + lseg * 8);
            cpasync16(abase + GTILE_H * 2 + off, Bg + (size_t)row * C_ + kpos + lseg * 8);
        }
        asm volatile("cp.async.commit_group;" ::: "memory");
    };

    float acc[4][4][4] = {};

    issue(0, 0);
    issue(1, 1);

    const int ar = lane & 15, ah = lane >> 4;
    const int bgr = lane >> 3, bi = lane & 7;

    constexpr int NK = C_ / 32;                  // 32
    for (int kt = 0; kt < NK; kt++) {
        const int s = kt % GSTAGES;
        // retire stage kt (youngest pending beyond it: only kt+1, if issued)
        if (kt < NK - 1)
            asm volatile("cp.async.wait_group 1;" ::: "memory");
        else
            asm volatile("cp.async.wait_group 0;" ::: "memory");
        __syncthreads();   // stage kt visible; all warps done computing stage kt-1

        if (kt + 2 < NK) issue(kt + 2, (kt + 2) % GSTAGES);

        const unsigned baseA = sbase + s * GSTAGE_BYTES;
        const unsigned baseB = baseA + GTILE_H * 2;

        #pragma unroll
        for (int ks = 0; ks < 2; ks++) {
            unsigned afr[4][4], bfr[2][4];
            #pragma unroll
            for (int mt = 0; mt < 4; mt++) {
                unsigned ad = baseA +
                    (unsigned)((wm + mt * 16 + ar) * LDA_ + ks * 16 + ah * 8) * 2;
                ldm4(afr[mt], ad);
            }
            #pragma unroll
            for (int p = 0; p < 2; p++) {
                unsigned bd = baseB +
                    (unsigned)((wn + p * 16 + (bgr >> 1) * 8 + bi) * LDA_ + ks * 16 + (bgr & 1) * 8) * 2;
                ldm4(bfr[p], bd);
            }
            #pragma unroll
            for (int mt = 0; mt < 4; mt++)
                #pragma unroll
                for (int ng = 0; ng < 4; ng++)
                    mma_f16(acc[mt][ng], afr[mt],
                            bfr[ng >> 1][(ng & 1) * 2], bfr[ng >> 1][(ng & 1) * 2 + 1]);
        }
    }

    if (Ch) {
        // fp16 output, Q-segment (cols [1024,2048)) scaled by QSC_
        #pragma unroll
        for (int mt = 0; mt < 4; mt++)
            #pragma unroll
            for (int ng = 0; ng < 4; ng++) {
                int col = bn + wn + ng * 8 + (lane & 3) * 2;
                float qs = (col >= C_ && col < 2 * C_) ? QSC_ : 1.0f;
                int row = bm + wm + mt * 16 + (lane >> 2);
                __half* cp = Ch + (size_t)row * N + col;
                *(__half2*)cp =
                    __floats2half2_rn(acc[mt][ng][0] * qs, acc[mt][ng][1] * qs);
                *(__half2*)(cp + (size_t)8 * N) =
                    __floats2half2_rn(acc[mt][ng][2] * qs, acc[mt][ng][3] * qs);
            }
    } else {
        #pragma unroll
        for (int mt = 0; mt < 4; mt++)
            #pragma unroll
            for (int ng = 0; ng < 4; ng++) {
                float* cp = Cm + (size_t)(bm + wm + mt * 16 + (lane >> 2)) * N
                               + bn + wn + ng * 8 + (lane & 3) * 2;
                *(float2*)cp = make_float2(acc[mt][ng][0], acc[mt][ng][1]);
                *(float2*)(cp + (size_t)8 * N) = make_float2(acc[mt][ng][2], acc[mt][ng][3]);
            }
    }
}

// ---------------------------------------------------------------------------
// Tensor-core causal flash attention (fp16 mma, fp32 softmax/accum).
// Grid (T/64, B*H), 128 threads = 4 warps; warp w owns q-rows [16w,16w+16).
// Q pre-scaled by c^-0.5*log2e, so S fragments are directly exp2 arguments.
// qkvh layout [B,T,3C]: K|Q|V per head h at col h*64 (+0 / +C_ / +2C_).
// Output: fp16 (consumed by proj GEMM).
// ---------------------------------------------------------------------------
constexpr int LDH = 72;   // fp16 row stride (144B): conflict-free ldmatrix

__global__ __launch_bounds__(128)
void attn_mma_kernel(const __half* __restrict__ qkvh, __half* __restrict__ outp)
{
    __shared__ __align__(16) __half Qs[64 * LDH];
    __shared__ __align__(16) __half Ks[2][64 * LDH];
    __shared__ __align__(16) __half Vsm[2][64 * LDH];

    const int qb  = (int)gridDim.x - 1 - (int)blockIdx.x;   // heavy first
    const int bh  = blockIdx.y, b = bh >> 4, h = bh & 15;
    const int tid = threadIdx.x, lane = tid & 31, wid = tid >> 5;
    const int wrow = wid * 16;
    const size_t tok0 = (size_t)b * T_;
    const int qtok0 = qb * 64;

    // Load Q tile (64x64 fp16) to smem
    {
        const __half* src = qkvh + (tok0 + qtok0) * N1_ + C_ + h * HS_;
        #pragma unroll
        for (int u = 0; u < 4; u++) {
            int chunk = tid + u * 128;
            int r = chunk >> 3, sg = chunk & 7;
            *(uint4*)&Qs[r * LDH + sg * 8] = *(const uint4*)(src + (size_t)r * N1_ + sg * 8);
        }
    }

    auto issue_kv = [&](int kb, int buf) {
        const __half* ks = qkvh + (tok0 + kb * 64) * N1_ + h * HS_;
        const __half* vs = ks + 2 * C_;
        unsigned kd = smem_u32(Ks[buf]), vd = smem_u32(Vsm[buf]);
        #pragma unroll
        for (int u = 0; u < 4; u++) {
            int chunk = tid + u * 128;
            int r = chunk >> 3, sg = chunk & 7;
            unsigned so = (r * LDH + sg * 8) * 2;
            cpasync16(kd + so, ks + (size_t)r * N1_ + sg * 8);
            cpasync16(vd + so, vs + (size_t)r * N1_ + sg * 8);
        }
        asm volatile("cp.async.commit_group;" ::: "memory");
    };
    issue_kv(0, 0);

    __syncthreads();   // Qs ready

    // Build Q A-fragments (held in registers for whole kernel)
    const int roff = (lane & 7) + ((lane & 8) ? 8 : 0);
    const int coff = (lane & 16) ? 8 : 0;
    unsigned qa[4][4];
    #pragma unroll
    for (int ks = 0; ks < 4; ks++)
        ldm4(qa[ks], smem_u32(Qs) + (unsigned)(((wrow + roff) * LDH + ks * 16 + coff) * 2));

    float O[8][4];
    #pragma unroll
    for (int j = 0; j < 8; j++)
        #pragma unroll
        for (int c = 0; c < 4; c++) O[j][c] = 0.0f;
    float mz0 = -1e30f, mz1 = -1e30f, l0 = 0.0f, l1 = 0.0f;
    const int qr0 = wrow + (lane >> 2);      // local row in [0,64)
    const int qr1 = qr0 + 8;

    for (int kb = 0; kb <= qb; kb++) {
        const int buf = kb & 1;
        if (kb < qb) {
            issue_kv(kb + 1, buf ^ 1);
            asm volatile("cp.async.wait_group 1;" ::: "memory");
        } else {
            asm volatile("cp.async.wait_group 0;" ::: "memory");
        }
        __syncthreads();

        // S = Q @ K^T  (already in exp2-scaled units via Q pre-scale)
        float S[8][4];
        #pragma unroll
        for (int j = 0; j < 8; j++)
            #pragma unroll
            for (int c = 0; c < 4; c++) S[j][c] = 0.0f;

        const unsigned kbase = smem_u32(Ks[buf]);
        #pragma unroll
        for (int kg = 0; kg < 4; kg++)
            #pragma unroll
            for (int ng = 0; ng < 4; ng++) {
                unsigned r[4];
                ldm4(r, kbase + (unsigned)(((16 * ng + roff) * LDH + 16 * kg + coff) * 2));
                mma_f16(S[2 * ng],     qa[kg], r[0], r[2]);
                mma_f16(S[2 * ng + 1], qa[kg], r[1], r[3]);
            }

        // Causal mask (only diagonal block partial)
        if (kb == qb) {
            #pragma unroll
            for (int j = 0; j < 8; j++) {
                int k0 = 8 * j + 2 * (lane & 3);
                if (k0     > qr0) S[j][0] = -1e30f;
                if (k0 + 1 > qr0) S[j][1] = -1e30f;
                if (k0     > qr1) S[j][2] = -1e30f;
                if (k0 + 1 > qr1) S[j][3] = -1e30f;
            }
        }

        // Online softmax (base-2)
        float mx0 = -1e30f, mx1 = -1e30f;
        #pragma unroll
        for (int j = 0; j < 8; j++) {
            mx0 = fmaxf(mx0, fmaxf(S[j][0], S[j][1]));
            mx1 = fmaxf(mx1, fmaxf(S[j][2], S[j][3]));
        }
        mx0 = fmaxf(mx0, __shfl_xor_sync(0xffffffffu, mx0, 1));
        mx0 = fmaxf(mx0, __shfl_xor_sync(0xffffffffu, mx0, 2));
        mx1 = fmaxf(mx1, __shfl_xor_sync(0xffffffffu, mx1, 1));
        mx1 = fmaxf(mx1, __shfl_xor_sync(0xffffffffu, mx1, 2));
        const float mn0 = fmaxf(mz0, mx0), mn1 = fmaxf(mz1, mx1);
        const float f0 = ex2(mz0 - mn0), f1 = ex2(mz1 - mn1);
        mz0 = mn0; mz1 = mn1;

        float s0 = 0.0f, s1 = 0.0f;
        #pragma unroll
        for (int j = 0; j < 8; j++) {
            S[j][0] = ex2(S[j][0] - mn0); s0 += S[j][0];
            S[j][1] = ex2(S[j][1] - mn0); s0 += S[j][1];
            S[j][2] = ex2(S[j][2] - mn1); s1 += S[j][2];
            S[j][3] = ex2(S[j][3] - mn1); s1 += S[j][3];
        }
        s0 += __shfl_xor_sync(0xffffffffu, s0, 1);
        s0 += __shfl_xor_sync(0xffffffffu, s0, 2);
        s1 += __shfl_xor_sync(0xffffffffu, s1, 1);
        s1 += __shfl_xor_sync(0xffffffffu, s1, 2);
        l0 = l0 * f0 + s0;
        l1 = l1 * f1 + s1;
        #pragma unroll
        for (int j = 0; j < 8; j++) {
            O[j][0] *= f0; O[j][1] *= f0;
            O[j][2] *= f1; O[j][3] *= f1;
        }

        // O += P @ V  (P fragments built in registers from S)
        const unsigned vbase = smem_u32(Vsm[buf]);
        #pragma unroll
        for (int kg = 0; kg < 4; kg++) {
            unsigned ap[4];
            ap[0] = h2pack(S[2 * kg][0],     S[2 * kg][1]);
            ap[1] = h2pack(S[2 * kg][2],     S[2 * kg][3]);
            ap[2] = h2pack(S[2 * kg + 1][0], S[2 * kg + 1][1]);
            ap[3] = h2pack(S[2 * kg + 1][2], S[2 * kg + 1][3]);
            #pragma unroll
            for (int dg = 0; dg < 4; dg++) {
                unsigned r[4];
                ldm4t(r, vbase + (unsigned)(((16 * kg + roff) * LDH + 16 * dg + coff) * 2));
                mma_f16(O[2 * dg],     ap, r[0], r[1]);
                mma_f16(O[2 * dg + 1], ap, r[2], r[3]);
            }
        }
        __syncthreads();   // safe to overwrite buf next iteration
    }

    // Normalize and store fp16
    const float inv0 = 1.0f / l0, inv1 = 1.0f / l1;
    __half* op0 = outp + (tok0 + qtok0 + qr0) * C_ + h * HS_ + 2 * (lane & 3);
    __half* op1 = op0 + (size_t)8 * C_;
    #pragma unroll
    for (int j = 0; j < 8; j++) {
        *(__half2*)(op0 + 8 * j) = __floats2half2_rn(O[j][0] * inv0, O[j][1] * inv0);
        *(__half2*)(op1 + 8 * j) = __floats2half2_rn(O[j][2] * inv1, O[j][3] * inv1);
    }
}

// ---------------------------------------------------------------------------
// Launch
// ---------------------------------------------------------------------------
extern "C" void kernel_launch(void* const* d_in, const int* in_sizes, int n_in,
                              void* d_out, int out_size)
{
    const float* X = nullptr; const float* Wqkv = nullptr; const float* Wproj = nullptr;
    for (int i = 0; i < n_in; i++) {
        if      (in_sizes[i] == M_ * C_)   X     = (const float*)d_in[i];
        else if (in_sizes[i] == C_ * N1_)  Wqkv  = (const float*)d_in[i];
        else if (in_sizes[i] == C_ * C_)   Wproj = (const float*)d_in[i];
    }
    float* out = (float*)d_out;

    __half *qkvh, *atth, *Xh, *WqT, *WpT;
    cudaGetSymbolAddress((void**)&qkvh, g_qkvh);
    cudaGetSymbolAddress((void**)&atth, g_atth);
    cudaGetSymbolAddress((void**)&Xh,   g_Xh);
    cudaGetSymbolAddress((void**)&WqT,  g_WqT);
    cudaGetSymbolAddress((void**)&WpT,  g_WpT);

    cudaFuncSetAttribute(gemm_mma_h_kernel,
                         cudaFuncAttributeMaxDynamicSharedMemorySize, GEMM_SMEM_BYTES);

    // 1) convert inputs to fp16 (weights transposed)
    conv_f2h_kernel<<<M_ * C_ / 4 / 256, 256>>>(X, Xh);
    conv_wT_h_kernel<<<dim3(N1_ / 32, C_ / 32), dim3(32, 8)>>>(Wqkv, WqT, N1_);
    conv_wT_h_kernel<<<dim3(C_ / 32,  C_ / 32), dim3(32, 8)>>>(Wproj, WpT, C_);

    // 2) qkv = X @ W_qkv -> fp16 (Q segment pre-scaled), K=1024
    gemm_mma_h_kernel<<<dim3(N1_ / 128, M_ / 128), 256, GEMM_SMEM_BYTES>>>(
        Xh, WqT, nullptr, qkvh, N1_);

    // 3) tensor-core flash attention -> fp16 atth
    attn_mma_kernel<<<dim3(T_ / 64, B_ * H_), 128>>>(qkvh, atth);

    // 4) out = att @ W_proj (fp32 out), K=1024
    gemm_mma_h_kernel<<<dim3(C_ / 128, M_ / 128), 256, GEMM_SMEM_BYTES>>>(
        atth, WpT, out, nullptr, C_);
}